// round 2
// baseline (speedup 1.0000x reference)
#include <cuda_runtime.h>

// diff[K, N, D] = x[None, :, :] - centroid[:, None, :]
// N=65536, K=32, D=64, fp32. Store-roofline problem: 536 MB out, 16 MB in.
// ILP=2: each thread owns TWO float4 of x (warp-stride apart for coalescing),
// writes 2*K = 64 streaming stores. Fewer CTAs, deeper store MLP.

#define N_PTS 65536
#define K_CENT 32
#define D_DIM 64
#define D4 (D_DIM / 4)            // 16 float4 per row
#define CENT_F4 (K_CENT * D4)     // 512 float4 = 8 KB
#define THREADS 256

__global__ void __launch_bounds__(THREADS, 8)
kmeans_diff_kernel(const float4* __restrict__ x,
                   const float4* __restrict__ cent,
                   float4* __restrict__ out) {
    __shared__ float4 sc[CENT_F4];

    // Stage centroid tile (8 KB) into shared once per block.
    for (int i = threadIdx.x; i < CENT_F4; i += blockDim.x)
        sc[i] = cent[i];
    __syncthreads();

    // Each block covers 2*THREADS consecutive float4 of x.
    const unsigned base = blockIdx.x * (2 * THREADS) + threadIdx.x;
    const unsigned idx0 = base;            // first x-vec
    const unsigned idx1 = base + THREADS;  // second x-vec (warp-coalesced)
    const unsigned d0 = idx0 & (D4 - 1);
    const unsigned d1 = idx1 & (D4 - 1);   // == d0 since THREADS % D4 == 0, kept general

    const float4 xv0 = x[idx0];
    const float4 xv1 = x[idx1];

    const size_t plane = (size_t)N_PTS * D4;  // float4 elements per k-plane

#pragma unroll
    for (int k = 0; k < K_CENT; k++) {
        const float4 c0 = sc[k * D4 + d0];
        const float4 c1 = sc[k * D4 + d1];
        float4 r0, r1;
        r0.x = xv0.x - c0.x; r0.y = xv0.y - c0.y;
        r0.z = xv0.z - c0.z; r0.w = xv0.w - c0.w;
        r1.x = xv1.x - c1.x; r1.y = xv1.y - c1.y;
        r1.z = xv1.z - c1.z; r1.w = xv1.w - c1.w;
        const size_t p = (size_t)k * plane;
        // Streaming stores: write-once data, keep L2 for x.
        __stcs(out + p + idx0, r0);
        __stcs(out + p + idx1, r1);
    }
}

extern "C" void kernel_launch(void* const* d_in, const int* in_sizes, int n_in,
                              void* d_out, int out_size) {
    const float4* x    = (const float4*)d_in[0];   // [N, D] fp32
    const float4* cent = (const float4*)d_in[1];   // [K, D] fp32
    float4* out        = (float4*)d_out;           // [K, N, D] fp32

    const int total_f4 = N_PTS * D4;                  // 1,048,576
    const int blocks = total_f4 / (2 * THREADS);      // 2048
    kmeans_diff_kernel<<<blocks, THREADS>>>(x, cent, out);
}

// round 3
// speedup vs baseline: 1.1020x; 1.1020x over previous
#include <cuda_runtime.h>

// diff[K, N, D] = x[None, :, :] - centroid[:, None, :]
// N=65536, K=32, D=64, fp32. Store-roofline: 536 MB out.
// K split across blockIdx.y (KG k's per CTA) to reduce the number of
// concurrent DRAM write streams (row-buffer locality), while keeping
// per-thread store MLP = KG = 4 (enough to hide DRAM latency / TLB PTW).
// x is re-read gridDim.y times but stays L2-resident (16 MB << 126 MB L2).

#define N_PTS 65536
#define K_CENT 32
#define D_DIM 64
#define D4 (D_DIM / 4)            // 16 float4 per row
#define KG 4                      // k's per CTA
#define KY (K_CENT / KG)          // gridDim.y = 8
#define CENT_F4 (KG * D4)         // 64 float4 = 1 KB staged per CTA
#define THREADS 256

__global__ void __launch_bounds__(THREADS, 8)
kmeans_diff_kernel(const float4* __restrict__ x,
                   const float4* __restrict__ cent,
                   float4* __restrict__ out) {
    __shared__ float4 sc[CENT_F4];

    const int k0 = blockIdx.y * KG;

    // Stage this CTA's KG centroid rows (1 KB) into shared.
    for (int i = threadIdx.x; i < CENT_F4; i += blockDim.x)
        sc[i] = cent[k0 * D4 + i];
    __syncthreads();

    const unsigned idx = blockIdx.x * THREADS + threadIdx.x;  // [0, N*D/4)
    const unsigned d4 = idx & (D4 - 1);

    const float4 xv = x[idx];  // DRAM first wave, L2 hit afterwards

    const size_t plane = (size_t)N_PTS * D4;  // float4 per k-plane
    float4* o = out + (size_t)k0 * plane + idx;

#pragma unroll
    for (int kk = 0; kk < KG; kk++) {
        const float4 c = sc[kk * D4 + d4];
        float4 r;
        r.x = xv.x - c.x;
        r.y = xv.y - c.y;
        r.z = xv.z - c.z;
        r.w = xv.w - c.w;
        __stcs(o, r);            // streaming: write-once, keep x in L2
        o += plane;
    }
}

extern "C" void kernel_launch(void* const* d_in, const int* in_sizes, int n_in,
                              void* d_out, int out_size) {
    const float4* x    = (const float4*)d_in[0];   // [N, D] fp32
    const float4* cent = (const float4*)d_in[1];   // [K, D] fp32
    float4* out        = (float4*)d_out;           // [K, N, D] fp32

    const int total_f4 = N_PTS * D4;               // 1,048,576
    dim3 grid(total_f4 / THREADS, KY);             // (4096, 8)
    kmeans_diff_kernel<<<grid, THREADS>>>(x, cent, out);
}